// round 12
// baseline (speedup 1.0000x reference)
#include <cuda_runtime.h>
#include <cstdint>

// VTBPR fused kernel (R12): R11 structure, 4 rows per 512-thread CTA.
//   score[b] = item_beta[i] + user_beta[u] + <ug,ig> + <tv,vf_b> + <tt,tf_b>
//   metapath[b,0,p,l,:] = ug if path_type==0, ig if ==1, else 0
//
// d_out = [ score (B floats) | metapath (B*16*512 floats) ]
//
// Established R2-R11: kernel is at the DRAM mixed-stream ceiling
// (~5.5TB/s, 268MB writes + ~42MB read misses), invariant to occupancy
// (26-88%), store path (STG/UBLKCP), L2 policy (.cs/.wt/evict_last),
// ordering and batching. R11 (2 rows/CTA) gave the best kernel time
// (56.13us) and issue%; R12 extends to 4 rows/CTA (2048 CTAs) to remove
// the remaining per-CTA fixed cost. Per-thread code identical; rows run
// in parallel in disjoint quarter-blocks.

#define HIDDEN 512
#define VEC    (HIDDEN / 4)   // 128 float4 lanes per row
#define PL     16             // P*L
#define RPC    4              // rows per CTA
#define NT     (RPC * VEC)    // 512 threads

__device__ __forceinline__ uint64_t policy_evict_last() {
    uint64_t p;
    asm("createpolicy.fractional.L2::evict_last.b64 %0, 1.0;" : "=l"(p));
    return p;
}

__device__ __forceinline__ float4 ld_el(const float4* a, uint64_t pol) {
    float4 v;
    asm("ld.global.L2::cache_hint.v4.f32 {%0,%1,%2,%3}, [%4], %5;"
        : "=f"(v.x), "=f"(v.y), "=f"(v.z), "=f"(v.w)
        : "l"(a), "l"(pol));
    return v;
}

__global__ void __launch_bounds__(NT, 2)
vtbpr_kernel(const float* __restrict__ user_gama,
             const float* __restrict__ item_gama,
             const float* __restrict__ user_beta,
             const float* __restrict__ item_beta,
             const float* __restrict__ theta_user_visual,
             const float* __restrict__ theta_user_text,
             const float* __restrict__ visual_features,
             const float* __restrict__ textural_features,
             const int*   __restrict__ user_idx,
             const int*   __restrict__ item_idx,
             const int*   __restrict__ path_type,
             float* __restrict__ out,
             int B)
{
    const int tid  = threadIdx.x;          // 0..511
    const int sub  = tid >> 7;             // 0..3: which row this quarter owns
    const int lane = tid & (VEC - 1);      // 0..127 within the row
    const int b    = blockIdx.x * RPC + sub;

    __shared__ int   pt[RPC][PL];
    __shared__ float wsum[RPC][VEC / 32];

    const int u = user_idx[b];
    const int i = item_idx[b];

    // Stage all rows' path types (first 64 threads); hoist beta loads.
    if (tid < RPC * PL)
        pt[tid >> 4][tid & 15] = path_type[blockIdx.x * RPC * PL + tid];
    const float ub = user_beta[u];
    const float ib = item_beta[i];

    const uint64_t pol = policy_evict_last();

    const float4* ug_p = (const float4*)(user_gama         + (size_t)u * HIDDEN);
    const float4* ig_p = (const float4*)(item_gama         + (size_t)i * HIDDEN);
    const float4* tv_p = (const float4*)(theta_user_visual + (size_t)u * HIDDEN);
    const float4* tt_p = (const float4*)(theta_user_text   + (size_t)u * HIDDEN);
    const float4* vf_p = (const float4*)(visual_features   + (size_t)b * HIDDEN);
    const float4* tf_p = (const float4*)(textural_features + (size_t)b * HIDDEN);

    // Front-batch all six vector loads (max MLP), pinned evict_last in L2.
    const float4 ug4 = ld_el(&ug_p[lane], pol);
    const float4 ig4 = ld_el(&ig_p[lane], pol);
    const float4 tv4 = ld_el(&tv_p[lane], pol);
    const float4 tt4 = ld_el(&tt_p[lane], pol);
    const float4 vf4 = ld_el(&vf_p[lane], pol);
    const float4 tf4 = ld_el(&tf_p[lane], pol);

    // Dot products + warp reduce
    float partial =
        ug4.x * ig4.x + ug4.y * ig4.y + ug4.z * ig4.z + ug4.w * ig4.w +
        tv4.x * vf4.x + tv4.y * vf4.y + tv4.z * vf4.z + tv4.w * vf4.w +
        tt4.x * tf4.x + tt4.y * tf4.y + tt4.z * tf4.z + tt4.w * tf4.w;

    #pragma unroll
    for (int off = 16; off > 0; off >>= 1)
        partial += __shfl_xor_sync(0xFFFFFFFFu, partial, off);

    if ((tid & 31) == 0) wsum[sub][(tid >> 5) & 3] = partial;
    __syncthreads();   // orders pt STS + wsum

    if (lane == 0) {
        float s = ub + ib;
        #pragma unroll
        for (int w = 0; w < VEC / 32; w++) s += wsum[sub][w];
        out[b] = s;
    }

    // Metapath scatter: 16 coalesced STG.128 per thread per row.
    float4* mp = (float4*)(out + B + (size_t)b * PL * HIDDEN);
    const float4 zero4 = make_float4(0.f, 0.f, 0.f, 0.f);

    #pragma unroll
    for (int j = 0; j < PL; j++) {
        const int t = pt[sub][j];
        const float4 v = (t == 0) ? ug4 : ((t == 1) ? ig4 : zero4);
        mp[(size_t)j * VEC + lane] = v;
    }
}

extern "C" void kernel_launch(void* const* d_in, const int* in_sizes, int n_in,
                              void* d_out, int out_size)
{
    const float* user_gama          = (const float*)d_in[0];
    const float* item_gama          = (const float*)d_in[1];
    const float* user_beta          = (const float*)d_in[2];
    const float* item_beta          = (const float*)d_in[3];
    const float* theta_user_visual  = (const float*)d_in[4];
    const float* theta_user_text    = (const float*)d_in[5];
    const float* visual_features    = (const float*)d_in[6];
    const float* textural_features  = (const float*)d_in[7];
    const int*   user_idx           = (const int*)d_in[8];
    const int*   item_idx           = (const int*)d_in[9];
    const int*   path_type          = (const int*)d_in[10];

    const int B = in_sizes[8];  // 8192 (divisible by RPC)

    vtbpr_kernel<<<B / RPC, NT>>>(user_gama, item_gama, user_beta, item_beta,
                                  theta_user_visual, theta_user_text,
                                  visual_features, textural_features,
                                  user_idx, item_idx, path_type,
                                  (float*)d_out, B);
}

// round 13
// speedup vs baseline: 1.0299x; 1.0299x over previous
#include <cuda_runtime.h>
#include <cstdint>

// VTBPR fused kernel (R13): R11 (best measured: 56.13us ncu) with per-row
// named barriers instead of a CTA-wide __syncthreads.
//   score[b] = item_beta[i] + user_beta[u] + <ug,ig> + <tv,vf_b> + <tt,tf_b>
//   metapath[b,0,p,l,:] = ug if path_type==0, ig if ==1, else 0
//
// d_out = [ score (B floats) | metapath (B*16*512 floats) ]
//
// Established R2-R12: DRAM mixed-stream ceiling ~5.5TB/s; invariant to
// occupancy (26-88%), store path, L2 policy, ordering; row-batching
// optimum is 2 rows/CTA (R12's 4 rows regressed via barrier coupling of
// 16 skewed warps). R13 removes the last coupling: each row's 4 warps
// sync via bar.sync(1+half, 128), so neither row waits on the other's
// gather latency.

#define HIDDEN 512
#define VEC    (HIDDEN / 4)   // 128 float4 lanes per row
#define PL     16             // P*L
#define NT     256            // threads per CTA (2 rows)

__device__ __forceinline__ uint64_t policy_evict_last() {
    uint64_t p;
    asm("createpolicy.fractional.L2::evict_last.b64 %0, 1.0;" : "=l"(p));
    return p;
}

__device__ __forceinline__ float4 ld_el(const float4* a, uint64_t pol) {
    float4 v;
    asm("ld.global.L2::cache_hint.v4.f32 {%0,%1,%2,%3}, [%4], %5;"
        : "=f"(v.x), "=f"(v.y), "=f"(v.z), "=f"(v.w)
        : "l"(a), "l"(pol));
    return v;
}

__global__ void __launch_bounds__(NT, 4)
vtbpr_kernel(const float* __restrict__ user_gama,
             const float* __restrict__ item_gama,
             const float* __restrict__ user_beta,
             const float* __restrict__ item_beta,
             const float* __restrict__ theta_user_visual,
             const float* __restrict__ theta_user_text,
             const float* __restrict__ visual_features,
             const float* __restrict__ textural_features,
             const int*   __restrict__ user_idx,
             const int*   __restrict__ item_idx,
             const int*   __restrict__ path_type,
             float* __restrict__ out,
             int B)
{
    const int tid  = threadIdx.x;          // 0..255
    const int half = tid >> 7;             // 0/1: which row this half owns
    const int lane = tid & (VEC - 1);      // 0..127 within the row
    const int b    = blockIdx.x * 2 + half;

    __shared__ int   pt[2][PL];
    __shared__ float wsum[2][VEC / 32];

    const int u = user_idx[b];
    const int i = item_idx[b];

    // Each half stages its OWN row's path types (lanes 0..15 of the half).
    if (lane < PL) pt[half][lane] = path_type[b * PL + lane];
    const float ub = user_beta[u];
    const float ib = item_beta[i];

    const uint64_t pol = policy_evict_last();

    const float4* ug_p = (const float4*)(user_gama         + (size_t)u * HIDDEN);
    const float4* ig_p = (const float4*)(item_gama         + (size_t)i * HIDDEN);
    const float4* tv_p = (const float4*)(theta_user_visual + (size_t)u * HIDDEN);
    const float4* tt_p = (const float4*)(theta_user_text   + (size_t)u * HIDDEN);
    const float4* vf_p = (const float4*)(visual_features   + (size_t)b * HIDDEN);
    const float4* tf_p = (const float4*)(textural_features + (size_t)b * HIDDEN);

    // Front-batch all six vector loads (max MLP), pinned evict_last in L2.
    const float4 ug4 = ld_el(&ug_p[lane], pol);
    const float4 ig4 = ld_el(&ig_p[lane], pol);
    const float4 tv4 = ld_el(&tv_p[lane], pol);
    const float4 tt4 = ld_el(&tt_p[lane], pol);
    const float4 vf4 = ld_el(&vf_p[lane], pol);
    const float4 tf4 = ld_el(&tf_p[lane], pol);

    // Dot products + warp reduce
    float partial =
        ug4.x * ig4.x + ug4.y * ig4.y + ug4.z * ig4.z + ug4.w * ig4.w +
        tv4.x * vf4.x + tv4.y * vf4.y + tv4.z * vf4.z + tv4.w * vf4.w +
        tt4.x * tf4.x + tt4.y * tf4.y + tt4.z * tf4.z + tt4.w * tf4.w;

    #pragma unroll
    for (int off = 16; off > 0; off >>= 1)
        partial += __shfl_xor_sync(0xFFFFFFFFu, partial, off);

    if ((tid & 31) == 0) wsum[half][(tid >> 5) & 3] = partial;

    // Per-row barrier: only this row's 4 warps synchronize (pt + wsum).
    asm volatile("bar.sync %0, %1;" :: "r"(1 + half), "r"(VEC) : "memory");

    if (lane == 0) {
        float s = ub + ib;
        #pragma unroll
        for (int w = 0; w < VEC / 32; w++) s += wsum[half][w];
        out[b] = s;
    }

    // Metapath scatter: 16 coalesced STG.128 per thread for this row.
    float4* mp = (float4*)(out + B + (size_t)b * PL * HIDDEN);
    const float4 zero4 = make_float4(0.f, 0.f, 0.f, 0.f);

    #pragma unroll
    for (int j = 0; j < PL; j++) {
        const int t = pt[half][j];
        const float4 v = (t == 0) ? ug4 : ((t == 1) ? ig4 : zero4);
        mp[(size_t)j * VEC + lane] = v;
    }
}

extern "C" void kernel_launch(void* const* d_in, const int* in_sizes, int n_in,
                              void* d_out, int out_size)
{
    const float* user_gama          = (const float*)d_in[0];
    const float* item_gama          = (const float*)d_in[1];
    const float* user_beta          = (const float*)d_in[2];
    const float* item_beta          = (const float*)d_in[3];
    const float* theta_user_visual  = (const float*)d_in[4];
    const float* theta_user_text    = (const float*)d_in[5];
    const float* visual_features    = (const float*)d_in[6];
    const float* textural_features  = (const float*)d_in[7];
    const int*   user_idx           = (const int*)d_in[8];
    const int*   item_idx           = (const int*)d_in[9];
    const int*   path_type          = (const int*)d_in[10];

    const int B = in_sizes[8];  // 8192 (even)

    vtbpr_kernel<<<B / 2, NT>>>(user_gama, item_gama, user_beta, item_beta,
                                theta_user_visual, theta_user_text,
                                visual_features, textural_features,
                                user_idx, item_idx, path_type,
                                (float*)d_out, B);
}